// round 4
// baseline (speedup 1.0000x reference)
#include <cuda_runtime.h>
#include <cuda_bf16.h>

// Problem constants (fixed by the reference)
#define BATCH      512
#define SEQ        200
#define HALF       100   // t-range per block
#define EMB        256
#define NUM_SKILLS 300
#define D3         21    // CURVE_DIM//3
#define DM         22    // D3 + CURVE_DIM%3

// Fused single kernel.
// Grid = BATCH*2 blocks, 256 threads. Block handles batch row b = blockIdx.x>>1,
// t in [half*100, half*100+100).
//
// Phase 0: fold proj_w/proj_b + the six tiny Linear(1,d) params into per-block
//          smem basis vectors sA..sD:  traj[e] = qf*A[e] + att*B[e] + mast*C[e] + D[e]
// Phase 1: running counts by direct counting (O(t) per t, parallel over t)
// Phase 2: stream 1KB output rows, fully coalesced float4 streaming stores.
__global__ __launch_bounds__(256) void te_fused(const int* __restrict__ q,
                                                const int* __restrict__ r,
                                                const float* __restrict__ skill_w,
                                                const float* __restrict__ skill_b,
                                                const float* __restrict__ att_w,
                                                const float* __restrict__ att_b,
                                                const float* __restrict__ mast_w,
                                                const float* __restrict__ mast_b,
                                                const float* __restrict__ proj_w,
                                                const float* __restrict__ proj_b,
                                                float* __restrict__ out) {
    __shared__ __align__(16) float sA[EMB];
    __shared__ __align__(16) float sB[EMB];
    __shared__ __align__(16) float sC[EMB];
    __shared__ __align__(16) float sD[EMB];
    __shared__ int   sq[SEQ];
    __shared__ int   sr[SEQ];
    __shared__ float s_qf[HALF];
    __shared__ float s_att[HALF];
    __shared__ float s_mast[HALF];
    __shared__ float s_val[HALF];

    const int b   = blockIdx.x >> 1;
    const int t0  = (blockIdx.x & 1) * HALF;
    const int tid = threadIdx.x;

    // ---- Phase 0: per-block basis fold (every thread owns one embedding e) ----
    {
        const int e = tid;                       // 0..255
        const float* row = proj_w + e * 64;      // proj_w is [EMB,64] row-major
        float a = 0.f, bb = 0.f, c = 0.f, d = proj_b[e];
#pragma unroll
        for (int i = 0; i < D3; i++) {
            float w = row[i];
            a = fmaf(skill_w[i], w, a);
            d = fmaf(skill_b[i], w, d);
        }
#pragma unroll
        for (int i = 0; i < D3; i++) {
            float w = row[D3 + i];
            bb = fmaf(att_w[i], w, bb);
            d  = fmaf(att_b[i], w, d);
        }
#pragma unroll
        for (int i = 0; i < DM; i++) {
            float w = row[2 * D3 + i];
            c = fmaf(mast_w[i], w, c);
            d = fmaf(mast_b[i], w, d);
        }
        sA[e] = a; sB[e] = bb; sC[e] = c; sD[e] = d;
    }

    // ---- load full q/r row (need history from t=0 even for second half) ----
    if (tid < SEQ) {
        sq[tid] = q[b * SEQ + tid];
        sr[tid] = r[b * SEQ + tid];
    }
    __syncthreads();

    // ---- Phase 1: counts for this block's HALF t's ----
    if (tid < HALF) {
        const int t  = t0 + tid;
        const int qt = sq[t];
        int att = 0, cor = 0;
        for (int tp = 0; tp <= t; tp++) {
            int qp = sq[tp];                     // warp-broadcast smem read
            if ((unsigned)qp < NUM_SKILLS && qp == qt) {
                att += 1;
                cor += sr[tp];
            }
        }
        const float v  = ((unsigned)qt < NUM_SKILLS) ? 1.0f : 0.0f;
        const float af = (float)att;
        // fold validity mask into the scalars (D term handled via s_val)
        s_qf[tid]   = v * (float)qt;
        s_att[tid]  = v * af;
        s_mast[tid] = v * ((float)cor / fmaxf(af, 1.0f));
        s_val[tid]  = v;
    }
    __syncthreads();

    // ---- Phase 2: stream output. 4 t-subgroups x 64 lanes; each lane owns a
    //      float4 slice of the 256-wide embedding -> 1KB coalesced stores. ----
    const int lane = tid & 63;   // float4 index within embedding row
    const int tg   = tid >> 6;   // 0..3

    const float4 A = reinterpret_cast<const float4*>(sA)[lane];
    const float4 Bv = reinterpret_cast<const float4*>(sB)[lane];
    const float4 C = reinterpret_cast<const float4*>(sC)[lane];
    const float4 D = reinterpret_cast<const float4*>(sD)[lane];

    float4* __restrict__ out4 = reinterpret_cast<float4*>(out);

#pragma unroll 5
    for (int i = tg; i < HALF; i += 4) {
        const float qf = s_qf[i];
        const float at = s_att[i];
        const float ms = s_mast[i];
        const float v  = s_val[i];
        float4 o;
        o.x = fmaf(qf, A.x, fmaf(at, Bv.x, fmaf(ms, C.x, v * D.x)));
        o.y = fmaf(qf, A.y, fmaf(at, Bv.y, fmaf(ms, C.y, v * D.y)));
        o.z = fmaf(qf, A.z, fmaf(at, Bv.z, fmaf(ms, C.z, v * D.z)));
        o.w = fmaf(qf, A.w, fmaf(at, Bv.w, fmaf(ms, C.w, v * D.w)));
        // Write-once output: streaming store, skip L2 retention
        __stcs(&out4[(size_t)(b * SEQ + t0 + i) * (EMB / 4) + lane], o);
    }
}

extern "C" void kernel_launch(void* const* d_in, const int* in_sizes, int n_in,
                              void* d_out, int out_size) {
    // metadata order: q, r, qry, skill_w, skill_b, att_w, att_b,
    //                 mast_w, mast_b, proj_w, proj_b
    const int*   q       = (const int*)d_in[0];
    const int*   r       = (const int*)d_in[1];
    // d_in[2] = qry — unused by the reference
    const float* skill_w = (const float*)d_in[3];
    const float* skill_b = (const float*)d_in[4];
    const float* att_w   = (const float*)d_in[5];
    const float* att_b   = (const float*)d_in[6];
    const float* mast_w  = (const float*)d_in[7];
    const float* mast_b  = (const float*)d_in[8];
    const float* proj_w  = (const float*)d_in[9];
    const float* proj_b  = (const float*)d_in[10];
    float* out = (float*)d_out;

    te_fused<<<BATCH * 2, 256>>>(q, r, skill_w, skill_b, att_w, att_b,
                                 mast_w, mast_b, proj_w, proj_b, out);
}

// round 5
// speedup vs baseline: 3.4777x; 3.4777x over previous
#include <cuda_runtime.h>
#include <cuda_bf16.h>

// Problem constants (fixed by the reference)
#define BATCH      512
#define SEQ        200
#define HALF       100   // t-range per te_main block
#define EMB        256
#define NUM_SKILLS 300
#define D3         21    // CURVE_DIM//3
#define DM         22    // D3 + CURVE_DIM%3

// Precomputed affine basis: traj[b,t,e] = qf*A[e] + att*B[e] + mast*C[e] + D[e]
__device__ __align__(16) float g_A[EMB];
__device__ __align__(16) float g_B[EMB];
__device__ __align__(16) float g_C[EMB];
__device__ __align__(16) float g_D[EMB];

// ---------------------------------------------------------------------------
// Precompute: warp-per-embedding-row, fully coalesced.
// Grid 8 x 256 threads = 64 warps; each warp folds 4 rows of proj_w [EMB,64].
// Lane l covers columns l and l+32 (two coalesced 128B line loads per row),
// then 4 butterfly reductions produce A,B,C,D for that e.
// ---------------------------------------------------------------------------
__global__ __launch_bounds__(256) void te_precompute(const float* __restrict__ skill_w,
                                                     const float* __restrict__ skill_b,
                                                     const float* __restrict__ att_w,
                                                     const float* __restrict__ att_b,
                                                     const float* __restrict__ mast_w,
                                                     const float* __restrict__ mast_b,
                                                     const float* __restrict__ proj_w,
                                                     const float* __restrict__ proj_b) {
    const int lane = threadIdx.x & 31;
    const int wid  = (blockIdx.x * blockDim.x + threadIdx.x) >> 5;  // global warp 0..63

    // Per-lane segment weights (hoisted across the 4 rows this warp handles).
    // col0 = lane (0..31): seg skill if <21 else att(idx col0-21)
    // col1 = lane+32 (32..63): seg att if <42 (idx col1-21) else mast(idx col1-42)
    const int   c1  = lane + 32;
    const float w0  = (lane < D3) ? skill_w[lane] : att_w[lane - D3];
    const float bw0 = (lane < D3) ? skill_b[lane] : att_b[lane - D3];
    const float w1  = (c1 < 2 * D3) ? att_w[c1 - D3] : mast_w[c1 - 2 * D3];
    const float bw1 = (c1 < 2 * D3) ? att_b[c1 - D3] : mast_b[c1 - 2 * D3];
    const bool  seg0_is_a = (lane < D3);
    const bool  seg1_is_b = (c1 < 2 * D3);

#pragma unroll
    for (int j = 0; j < 4; j++) {
        const int e = wid * 4 + j;
        const float x0 = proj_w[e * 64 + lane];   // coalesced
        const float x1 = proj_w[e * 64 + c1];     // coalesced

        const float t0 = w0 * x0;
        const float t1 = w1 * x1;
        float pa = seg0_is_a ? t0 : 0.f;
        float pb = (seg0_is_a ? 0.f : t0) + (seg1_is_b ? t1 : 0.f);
        float pc = seg1_is_b ? 0.f : t1;
        float pd = fmaf(bw0, x0, bw1 * x1);

#pragma unroll
        for (int off = 16; off >= 1; off >>= 1) {
            pa += __shfl_xor_sync(0xffffffffu, pa, off);
            pb += __shfl_xor_sync(0xffffffffu, pb, off);
            pc += __shfl_xor_sync(0xffffffffu, pc, off);
            pd += __shfl_xor_sync(0xffffffffu, pd, off);
        }
        if (lane == 0) {
            g_A[e] = pa;
            g_B[e] = pb;
            g_C[e] = pc;
            g_D[e] = pd + proj_b[e];
        }
    }
}

// ---------------------------------------------------------------------------
// Main: 1024 blocks (2 per batch row) x 256 threads.
// Phase 1: running counts for this block's HALF t's (history from t=0).
// Phase 2: 4 t-subgroups x 64 lanes, each lane owns a float4 of the 256-wide
//          output row -> 1KB fully-coalesced streaming stores.
// ---------------------------------------------------------------------------
__global__ __launch_bounds__(256) void te_main(const int* __restrict__ q,
                                               const int* __restrict__ r,
                                               float* __restrict__ out) {
    __shared__ int    sq[SEQ];
    __shared__ int    sr[SEQ];
    __shared__ __align__(16) float4 s_scal[HALF];  // {qf, att, mast, valid}

    const int b   = blockIdx.x >> 1;
    const int t0  = (blockIdx.x & 1) * HALF;
    const int tid = threadIdx.x;

    if (tid < SEQ) {
        sq[tid] = q[b * SEQ + tid];
        sr[tid] = r[b * SEQ + tid];
    }
    __syncthreads();

    // Phase 1: attempts[t] = #{t' <= t : valid(t') && q[t']==q[t]}, correct w/ r.
    if (tid < HALF) {
        const int t  = t0 + tid;
        const int qt = sq[t];
        int att = 0, cor = 0;
        for (int tp = 0; tp <= t; tp++) {
            int qp = sq[tp];                    // warp-broadcast smem read
            if ((unsigned)qp < NUM_SKILLS && qp == qt) {
                att += 1;
                cor += sr[tp];
            }
        }
        const float v  = ((unsigned)qt < NUM_SKILLS) ? 1.0f : 0.0f;
        const float af = (float)att;
        s_scal[tid] = make_float4(v * (float)qt,
                                  v * af,
                                  v * ((float)cor / fmaxf(af, 1.0f)),
                                  v);
    }
    __syncthreads();

    // Phase 2
    const int lane = tid & 63;   // float4 index within the 256-wide row
    const int tg   = tid >> 6;   // 0..3

    const float4 A  = reinterpret_cast<const float4*>(g_A)[lane];
    const float4 Bv = reinterpret_cast<const float4*>(g_B)[lane];
    const float4 C  = reinterpret_cast<const float4*>(g_C)[lane];
    const float4 D  = reinterpret_cast<const float4*>(g_D)[lane];

    float4* __restrict__ out4 = reinterpret_cast<float4*>(out);

#pragma unroll 5
    for (int i = tg; i < HALF; i += 4) {
        const float4 s = s_scal[i];   // one LDS.128
        float4 o;
        o.x = fmaf(s.x, A.x, fmaf(s.y, Bv.x, fmaf(s.z, C.x, s.w * D.x)));
        o.y = fmaf(s.x, A.y, fmaf(s.y, Bv.y, fmaf(s.z, C.y, s.w * D.y)));
        o.z = fmaf(s.x, A.z, fmaf(s.y, Bv.z, fmaf(s.z, C.z, s.w * D.z)));
        o.w = fmaf(s.x, A.w, fmaf(s.y, Bv.w, fmaf(s.z, C.w, s.w * D.w)));
        __stcs(&out4[(size_t)(b * SEQ + t0 + i) * (EMB / 4) + lane], o);
    }
}

extern "C" void kernel_launch(void* const* d_in, const int* in_sizes, int n_in,
                              void* d_out, int out_size) {
    // metadata order: q, r, qry, skill_w, skill_b, att_w, att_b,
    //                 mast_w, mast_b, proj_w, proj_b
    const int*   q       = (const int*)d_in[0];
    const int*   r       = (const int*)d_in[1];
    // d_in[2] = qry — unused by the reference
    const float* skill_w = (const float*)d_in[3];
    const float* skill_b = (const float*)d_in[4];
    const float* att_w   = (const float*)d_in[5];
    const float* att_b   = (const float*)d_in[6];
    const float* mast_w  = (const float*)d_in[7];
    const float* mast_b  = (const float*)d_in[8];
    const float* proj_w  = (const float*)d_in[9];
    const float* proj_b  = (const float*)d_in[10];
    float* out = (float*)d_out;

    te_precompute<<<8, 256>>>(skill_w, skill_b, att_w, att_b,
                              mast_w, mast_b, proj_w, proj_b);
    te_main<<<BATCH * 2, 256>>>(q, r, out);
}

// round 6
// speedup vs baseline: 3.4903x; 1.0036x over previous
#include <cuda_runtime.h>
#include <cuda_bf16.h>

// Problem constants (fixed by the reference)
#define BATCH      512
#define SEQ        200
#define HALF       100   // t-range per te_main block
#define EMB        256
#define NUM_SKILLS 300
#define D3         21    // CURVE_DIM//3
#define DM         22    // D3 + CURVE_DIM%3

// Precomputed affine basis: traj[b,t,e] = qf*A[e] + att*B[e] + mast*C[e] + D[e]
__device__ __align__(16) float g_A[EMB];
__device__ __align__(16) float g_B[EMB];
__device__ __align__(16) float g_C[EMB];
__device__ __align__(16) float g_D[EMB];

// ---------------------------------------------------------------------------
// Precompute: warp-per-embedding-row, fully coalesced. 8 blocks x 256 threads.
// ---------------------------------------------------------------------------
__global__ __launch_bounds__(256) void te_precompute(const float* __restrict__ skill_w,
                                                     const float* __restrict__ skill_b,
                                                     const float* __restrict__ att_w,
                                                     const float* __restrict__ att_b,
                                                     const float* __restrict__ mast_w,
                                                     const float* __restrict__ mast_b,
                                                     const float* __restrict__ proj_w,
                                                     const float* __restrict__ proj_b) {
    const int lane = threadIdx.x & 31;
    const int wid  = (blockIdx.x * blockDim.x + threadIdx.x) >> 5;  // global warp 0..63

    const int   c1  = lane + 32;
    const float w0  = (lane < D3) ? skill_w[lane] : att_w[lane - D3];
    const float bw0 = (lane < D3) ? skill_b[lane] : att_b[lane - D3];
    const float w1  = (c1 < 2 * D3) ? att_w[c1 - D3] : mast_w[c1 - 2 * D3];
    const float bw1 = (c1 < 2 * D3) ? att_b[c1 - D3] : mast_b[c1 - 2 * D3];
    const bool  seg0_is_a = (lane < D3);
    const bool  seg1_is_b = (c1 < 2 * D3);

#pragma unroll
    for (int j = 0; j < 4; j++) {
        const int e = wid * 4 + j;
        const float x0 = proj_w[e * 64 + lane];   // coalesced
        const float x1 = proj_w[e * 64 + c1];     // coalesced

        const float t0 = w0 * x0;
        const float t1 = w1 * x1;
        float pa = seg0_is_a ? t0 : 0.f;
        float pb = (seg0_is_a ? 0.f : t0) + (seg1_is_b ? t1 : 0.f);
        float pc = seg1_is_b ? 0.f : t1;
        float pd = fmaf(bw0, x0, bw1 * x1);

#pragma unroll
        for (int off = 16; off >= 1; off >>= 1) {
            pa += __shfl_xor_sync(0xffffffffu, pa, off);
            pb += __shfl_xor_sync(0xffffffffu, pb, off);
            pc += __shfl_xor_sync(0xffffffffu, pc, off);
            pd += __shfl_xor_sync(0xffffffffu, pd, off);
        }
        if (lane == 0) {
            g_A[e] = pa;
            g_B[e] = pb;
            g_C[e] = pc;
            g_D[e] = pd + proj_b[e];
        }
    }
}

// ---------------------------------------------------------------------------
// Main: 1024 blocks (2 per batch row) x 256 threads, forced to 8 blocks/SM so
// the whole grid is ONE fully-resident wave (148*8 = 1184 >= 1024).
// ---------------------------------------------------------------------------
__global__ __launch_bounds__(256, 8) void te_main(const int* __restrict__ q,
                                                  const int* __restrict__ r,
                                                  float* __restrict__ out) {
    __shared__ int    sq[SEQ];
    __shared__ int    sr[SEQ];
    __shared__ __align__(16) float4 s_scal[HALF];  // {qf, att, mast, valid}

    const int b   = blockIdx.x >> 1;
    const int t0  = (blockIdx.x & 1) * HALF;
    const int tid = threadIdx.x;

    if (tid < SEQ) {
        sq[tid] = q[b * SEQ + tid];
        sr[tid] = r[b * SEQ + tid];
    }
    __syncthreads();

    // Phase 1: attempts[t] = #{t' <= t : valid(t') && q[t']==q[t]}, correct w/ r.
    if (tid < HALF) {
        const int t  = t0 + tid;
        const int qt = sq[t];
        int att = 0, cor = 0;
        for (int tp = 0; tp <= t; tp++) {
            int qp = sq[tp];                    // warp-broadcast smem read
            if ((unsigned)qp < NUM_SKILLS && qp == qt) {
                att += 1;
                cor += sr[tp];
            }
        }
        const float v  = ((unsigned)qt < NUM_SKILLS) ? 1.0f : 0.0f;
        const float af = (float)att;
        s_scal[tid] = make_float4(v * (float)qt,
                                  v * af,
                                  v * ((float)cor / fmaxf(af, 1.0f)),
                                  v);
    }
    __syncthreads();

    // Phase 2: 4 t-subgroups x 64 lanes; each lane owns a float4 of the
    // 256-wide row -> 1KB fully-coalesced streaming stores per t.
    const int lane = tid & 63;   // float4 index within the 256-wide row
    const int tg   = tid >> 6;   // 0..3

    const float4 A  = reinterpret_cast<const float4*>(g_A)[lane];
    const float4 Bv = reinterpret_cast<const float4*>(g_B)[lane];
    const float4 C  = reinterpret_cast<const float4*>(g_C)[lane];
    const float4 D  = reinterpret_cast<const float4*>(g_D)[lane];

    // Strength-reduced output pointer: start at (b*SEQ + t0 + tg) row, step 4 rows.
    float4* __restrict__ p = reinterpret_cast<float4*>(out)
                           + (size_t)(b * SEQ + t0 + tg) * (EMB / 4) + lane;

#pragma unroll 5
    for (int i = tg; i < HALF; i += 4, p += 4 * (EMB / 4)) {
        const float4 s = s_scal[i];   // one LDS.128, broadcast within warp
        float4 o;
        o.x = fmaf(s.x, A.x, fmaf(s.y, Bv.x, fmaf(s.z, C.x, s.w * D.x)));
        o.y = fmaf(s.x, A.y, fmaf(s.y, Bv.y, fmaf(s.z, C.y, s.w * D.y)));
        o.z = fmaf(s.x, A.z, fmaf(s.y, Bv.z, fmaf(s.z, C.z, s.w * D.z)));
        o.w = fmaf(s.x, A.w, fmaf(s.y, Bv.w, fmaf(s.z, C.w, s.w * D.w)));
        __stcs(p, o);
    }
}

extern "C" void kernel_launch(void* const* d_in, const int* in_sizes, int n_in,
                              void* d_out, int out_size) {
    // metadata order: q, r, qry, skill_w, skill_b, att_w, att_b,
    //                 mast_w, mast_b, proj_w, proj_b
    const int*   q       = (const int*)d_in[0];
    const int*   r       = (const int*)d_in[1];
    // d_in[2] = qry — unused by the reference
    const float* skill_w = (const float*)d_in[3];
    const float* skill_b = (const float*)d_in[4];
    const float* att_w   = (const float*)d_in[5];
    const float* att_b   = (const float*)d_in[6];
    const float* mast_w  = (const float*)d_in[7];
    const float* mast_b  = (const float*)d_in[8];
    const float* proj_w  = (const float*)d_in[9];
    const float* proj_b  = (const float*)d_in[10];
    float* out = (float*)d_out;

    te_precompute<<<8, 256>>>(skill_w, skill_b, att_w, att_b,
                              mast_w, mast_b, proj_w, proj_b);
    te_main<<<BATCH * 2, 256>>>(q, r, out);
}